// round 13
// baseline (speedup 1.0000x reference)
#include <cuda_runtime.h>
#include <cuda_bf16.h>
#include <cstdint>

#define N_NODES   50000
#define N_EDGES   600000
#define EMBED     128
#define HIDDEN    128
#define NUM_TYPES 16

// Scratch (device globals: allocation-free rule)
__device__ float g_x[N_NODES * EMBED];       // x (layer-1 input)
__device__ float g_agg[N_NODES * EMBED];     // neighbor MEAN (layer 1)
__device__ int   g_deg[N_NODES];
__device__ float g_z[N_NODES * NUM_TYPES];   // h1 @ Wlc
__device__ float g_r[N_NODES * NUM_TYPES];   // h1 @ Wrc + bf
__device__ float g_Wlc[HIDDEN * NUM_TYPES];  // W2_l @ Wc
__device__ float g_Wrc[HIDDEN * NUM_TYPES];  // W2_r @ Wc
__device__ float g_bf[NUM_TYPES];            // b2 @ Wc + bc
// bf16 hi/lo packed layer-1 weights, [n][kpair] (virtual K=256: Wl | Wr)
__device__ uint32_t g_Wh[HIDDEN * 128];
__device__ uint32_t g_Wlo[HIDDEN * 128];
// CSR (edges grouped by dst)
__device__ int g_rowptr[N_NODES + 1];
__device__ int g_cursor[N_NODES];
__device__ int g_csrc[N_EDGES];
__device__ int g_bsum[256];

// ---------------------------------------------------------------------------
// helpers
// ---------------------------------------------------------------------------
__device__ __forceinline__ void split2(float x, float y, uint32_t& hi, uint32_t& lo) {
    __nv_bfloat16 hx = __float2bfloat16(x), hy = __float2bfloat16(y);
    float rx = x - __bfloat162float(hx);
    float ry = y - __bfloat162float(hy);
    __nv_bfloat162 H; H.x = hx; H.y = hy;
    __nv_bfloat162 L; L.x = __float2bfloat16(rx); L.y = __float2bfloat16(ry);
    hi = *reinterpret_cast<uint32_t*>(&H);
    lo = *reinterpret_cast<uint32_t*>(&L);
}
__device__ __forceinline__ void mma16(float* d, const uint32_t* a, const uint32_t* b) {
    asm volatile(
        "mma.sync.aligned.m16n8k16.row.col.f32.bf16.bf16.f32 "
        "{%0,%1,%2,%3}, {%4,%5,%6,%7}, {%8,%9}, {%0,%1,%2,%3};"
        : "+f"(d[0]), "+f"(d[1]), "+f"(d[2]), "+f"(d[3])
        : "r"(a[0]), "r"(a[1]), "r"(a[2]), "r"(a[3]), "r"(b[0]), "r"(b[1]));
}

// ---------------------------------------------------------------------------
// Kernel: pre-pack W1_l|W1_r into bf16 hi/lo [n][kpair]
// ---------------------------------------------------------------------------
__global__ void k_wprep(const float* __restrict__ W1_l, const float* __restrict__ W1_r) {
    int idx = blockIdx.x * 256 + threadIdx.x;     // 0..16383
    if (idx >= HIDDEN * 128) return;
    int n  = idx >> 7;
    int kp = idx & 127;
    int k  = kp * 2;
    const float* Wsrc = (k < 128) ? W1_l : W1_r;
    int kk = k & 127;
    float v0 = Wsrc[kk * 128 + n];
    float v1 = Wsrc[(kk + 1) * 128 + n];
    uint32_t hi, lo;
    split2(v0, v1, hi, lo);
    g_Wh[n * 128 + kp]  = hi;
    g_Wlo[n * 128 + kp] = lo;
}

// ---------------------------------------------------------------------------
// Kernel: fold classifier into layer-2 weights.
// ---------------------------------------------------------------------------
__global__ void __launch_bounds__(128) k_wfuse(const float* __restrict__ W2_l,
                                               const float* __restrict__ W2_r,
                                               const float* __restrict__ Wc,
                                               const float* __restrict__ b2,
                                               const float* __restrict__ bc) {
    __shared__ float wcs[HIDDEN * NUM_TYPES];
    const int tid = threadIdx.x;
#pragma unroll
    for (int i = 0; i < 16; ++i) wcs[tid + i * 128] = Wc[tid + i * 128];
    __syncthreads();

    const float* Win = (blockIdx.x == 0) ? W2_l : W2_r;
    float* Wout      = (blockIdx.x == 0) ? g_Wlc : g_Wrc;

    float4 a0 = make_float4(0,0,0,0), a1 = a0, a2 = a0, a3 = a0;
    const float* row = Win + tid * HIDDEN;
#pragma unroll 4
    for (int t = 0; t < HIDDEN; ++t) {
        float w = row[t];
        float4 c0 = *(const float4*)&wcs[t * 16 + 0];
        float4 c1 = *(const float4*)&wcs[t * 16 + 4];
        float4 c2 = *(const float4*)&wcs[t * 16 + 8];
        float4 c3 = *(const float4*)&wcs[t * 16 + 12];
        a0.x = fmaf(w, c0.x, a0.x); a0.y = fmaf(w, c0.y, a0.y);
        a0.z = fmaf(w, c0.z, a0.z); a0.w = fmaf(w, c0.w, a0.w);
        a1.x = fmaf(w, c1.x, a1.x); a1.y = fmaf(w, c1.y, a1.y);
        a1.z = fmaf(w, c1.z, a1.z); a1.w = fmaf(w, c1.w, a1.w);
        a2.x = fmaf(w, c2.x, a2.x); a2.y = fmaf(w, c2.y, a2.y);
        a2.z = fmaf(w, c2.z, a2.z); a2.w = fmaf(w, c2.w, a2.w);
        a3.x = fmaf(w, c3.x, a3.x); a3.y = fmaf(w, c3.y, a3.y);
        a3.z = fmaf(w, c3.z, a3.z); a3.w = fmaf(w, c3.w, a3.w);
    }
    *(float4*)&Wout[tid * 16 + 0]  = a0;
    *(float4*)&Wout[tid * 16 + 4]  = a1;
    *(float4*)&Wout[tid * 16 + 8]  = a2;
    *(float4*)&Wout[tid * 16 + 12] = a3;

    if (blockIdx.x == 1 && tid < NUM_TYPES) {
        float s = bc[tid];
        for (int t = 0; t < HIDDEN; ++t) s = fmaf(b2[t], wcs[t * 16 + tid], s);
        g_bf[tid] = s;
    }
}

// ---------------------------------------------------------------------------
// Kernel 1: gather x = emb[entity], zero deg
// ---------------------------------------------------------------------------
__global__ void k_prep(const int* __restrict__ entity, const float* __restrict__ emb) {
    int node = blockIdx.x * 8 + (threadIdx.x >> 5);
    int lane = threadIdx.x & 31;
    if (node >= N_NODES) return;
    int e = entity[node];
    float4 v = ((const float4*)emb)[e * 32 + lane];
    ((float4*)g_x)[node * 32 + lane] = v;
    if (lane == 0) g_deg[node] = 0;
}

__global__ void k_deg(const int* __restrict__ dst) {
    int e = blockIdx.x * blockDim.x + threadIdx.x;
    if (e < N_EDGES) atomicAdd(&g_deg[dst[e]], 1);
}

// ---------------------------------------------------------------------------
// CSR build: block sums -> scan of sums -> per-block exclusive scan + fill.
// ---------------------------------------------------------------------------
__global__ void __launch_bounds__(256) k_scan1() {
    __shared__ int s[256];
    int idx = blockIdx.x * 256 + threadIdx.x;
    int v = (idx < N_NODES) ? g_deg[idx] : 0;
    s[threadIdx.x] = v;
    __syncthreads();
#pragma unroll
    for (int off = 128; off > 0; off >>= 1) {
        if (threadIdx.x < off) s[threadIdx.x] += s[threadIdx.x + off];
        __syncthreads();
    }
    if (threadIdx.x == 0) g_bsum[blockIdx.x] = s[0];
}

__global__ void __launch_bounds__(256) k_scan2(int nblocks) {
    __shared__ int s[256];
    int t = threadIdx.x;
    int v = (t < nblocks) ? g_bsum[t] : 0;
    s[t] = v;
    __syncthreads();
#pragma unroll
    for (int off = 1; off < 256; off <<= 1) {
        int x = (t >= off) ? s[t - off] : 0;
        __syncthreads();
        s[t] += x;
        __syncthreads();
    }
    if (t < nblocks) g_bsum[t] = s[t] - v;   // exclusive
}

__global__ void __launch_bounds__(256) k_scan3() {
    __shared__ int s[256];
    int idx = blockIdx.x * 256 + threadIdx.x;
    int t = threadIdx.x;
    int v = (idx < N_NODES) ? g_deg[idx] : 0;
    s[t] = v;
    __syncthreads();
#pragma unroll
    for (int off = 1; off < 256; off <<= 1) {
        int x = (t >= off) ? s[t - off] : 0;
        __syncthreads();
        s[t] += x;
        __syncthreads();
    }
    if (idx < N_NODES) {
        int excl = g_bsum[blockIdx.x] + s[t] - v;
        g_rowptr[idx] = excl;
        g_cursor[idx] = excl;
        if (idx == N_NODES - 1) g_rowptr[N_NODES] = excl + v;
    }
}

__global__ void k_fill(const int* __restrict__ src, const int* __restrict__ dst) {
    int e = blockIdx.x * blockDim.x + threadIdx.x;
    if (e >= N_EDGES) return;
    int d = dst[e];
    int pos = atomicAdd(&g_cursor[d], 1);
    g_csrc[pos] = src[e];
}

// ---------------------------------------------------------------------------
// Kernel: gather-aggregate 128-wide. One warp per node; writes the MEAN.
// ---------------------------------------------------------------------------
__global__ void __launch_bounds__(256) k_gather(void) {
    int node = blockIdx.x * 8 + (threadIdx.x >> 5);
    int lane = threadIdx.x & 31;
    if (node >= N_NODES) return;
    int start = g_rowptr[node];
    int end   = g_rowptr[node + 1];

    float4 a0 = make_float4(0.f, 0.f, 0.f, 0.f);
    float4 a1 = a0, a2 = a0, a3 = a0;
    int j = start;
    for (; j + 3 < end; j += 4) {
        int s0 = g_csrc[j];
        int s1 = g_csrc[j + 1];
        int s2 = g_csrc[j + 2];
        int s3 = g_csrc[j + 3];
        float4 v0 = ((const float4*)g_x)[s0 * 32 + lane];
        float4 v1 = ((const float4*)g_x)[s1 * 32 + lane];
        float4 v2 = ((const float4*)g_x)[s2 * 32 + lane];
        float4 v3 = ((const float4*)g_x)[s3 * 32 + lane];
        a0.x += v0.x; a0.y += v0.y; a0.z += v0.z; a0.w += v0.w;
        a1.x += v1.x; a1.y += v1.y; a1.z += v1.z; a1.w += v1.w;
        a2.x += v2.x; a2.y += v2.y; a2.z += v2.z; a2.w += v2.w;
        a3.x += v3.x; a3.y += v3.y; a3.z += v3.z; a3.w += v3.w;
    }
    for (; j < end; ++j) {
        int s0 = g_csrc[j];
        float4 v0 = ((const float4*)g_x)[s0 * 32 + lane];
        a0.x += v0.x; a0.y += v0.y; a0.z += v0.z; a0.w += v0.w;
    }
    int dg = end - start;
    float inv = 1.0f / (float)(dg > 1 ? dg : 1);
    float4 r = make_float4((a0.x + a1.x + a2.x + a3.x) * inv,
                           (a0.y + a1.y + a2.y + a3.y) * inv,
                           (a0.z + a1.z + a2.z + a3.z) * inv,
                           (a0.w + a1.w + a2.w + a3.w) * inv);
    ((float4*)g_agg)[node * 32 + lane] = r;
}

// ---------------------------------------------------------------------------
// Kernel 4: SAGE layer-1 (mma.sync bf16, 3-way split) with FUSED z/r epilogue:
//   h1 = relu(mean @ W1_l + b1 + x @ W1_r)   (in registers only)
//   z  = h1 @ Wlc ; r = h1 @ Wrc + bf        (written directly; h1 never stored)
// BM=128, BN=128, 8 warps (4m x 2n), double-buffered smem mainloop.
// Epilogue smem (reusing dsm as float*):
//   [0,2176)      Wlc staged [col][c] stride 17 (conflict-free)
//   [2176,4352)   Wrc staged
//   [4352,8448)   z/r accum [rowlocal][32] (c<16: z, else r)
//   [8448,8464)   bf
// ---------------------------------------------------------------------------
__global__ void __launch_bounds__(256, 2) k_layer_fused(
        const float* __restrict__ bias, const float* __restrict__ xin) {
    extern __shared__ uint32_t dsm[];

    const int tid = threadIdx.x;
    const int m0  = blockIdx.x * 128;

    uint32_t* sAh[2] = { dsm + 0 * 1536, dsm + 2 * 1536 };
    uint32_t* sAl[2] = { dsm + 1 * 1536, dsm + 3 * 1536 };
    uint32_t* sBh[2] = { dsm + 6144 + 0 * 1536, dsm + 6144 + 2 * 1536 };
    uint32_t* sBl[2] = { dsm + 6144 + 1 * 1536, dsm + 6144 + 3 * 1536 };

    const int w    = tid >> 5;
    const int lane = tid & 31;
    const int g    = lane >> 2;
    const int tg   = lane & 3;
    const int wm   = (w >> 1) << 5;     // 0,32,64,96
    const int wn   = (w & 1) << 6;      // 0,64

    const int a_m[2]  = { (tid + 0) >> 2,   (tid + 256) >> 2 };
    const int a_kq[2] = { (tid & 3) << 2,   (tid & 3) << 2 };
    const int b_n    = tid >> 1;
    const int b_half = (tid & 1) << 2;

    float acc[2][8][4];
#pragma unroll
    for (int mt = 0; mt < 2; ++mt)
#pragma unroll
        for (int nt = 0; nt < 8; ++nt)
#pragma unroll
            for (int q = 0; q < 4; ++q) acc[mt][nt][q] = 0.f;

    float4 aIn[2];
    uint4  bInH, bInL;

#define LOAD_AB(c) do {                                                        \
        const int kb = (c) * 16;                                               \
        _Pragma("unroll")                                                      \
        for (int it = 0; it < 2; ++it) {                                       \
            const int m  = a_m[it];                                            \
            const int gm = m0 + m;                                             \
            float4 v = make_float4(0.f, 0.f, 0.f, 0.f);                        \
            if (gm < N_NODES) {                                                \
                if (kb < 128) {                                                \
                    v = *(const float4*)(g_agg + (size_t)gm * 128 + kb + a_kq[it]); \
                } else {                                                       \
                    v = *(const float4*)(xin + (size_t)gm * 128 + (kb - 128) + a_kq[it]); \
                }                                                              \
            }                                                                  \
            aIn[it] = v;                                                       \
        }                                                                      \
        {                                                                      \
            const int goff = b_n * 128 + (c) * 8 + b_half;                     \
            bInH = *(const uint4*)&g_Wh[goff];                                 \
            bInL = *(const uint4*)&g_Wlo[goff];                                \
        }                                                                      \
    } while (0)

#define STORE_AB(buf) do {                                                     \
        _Pragma("unroll")                                                      \
        for (int it = 0; it < 2; ++it) {                                       \
            const float4 v = aIn[it];                                          \
            uint32_t h0, l0, h1, l1;                                           \
            split2(v.x, v.y, h0, l0);                                          \
            split2(v.z, v.w, h1, l1);                                          \
            const int base = a_m[it] * 12 + (a_kq[it] >> 1);                   \
            sAh[buf][base]     = h0;                                           \
            sAh[buf][base + 1] = h1;                                           \
            sAl[buf][base]     = l0;                                           \
            sAl[buf][base + 1] = l1;                                           \
        }                                                                      \
        {                                                                      \
            const int base = b_n * 12 + b_half;                                \
            *(uint4*)&sBh[buf][base] = bInH;                                   \
            *(uint4*)&sBl[buf][base] = bInL;                                   \
        }                                                                      \
    } while (0)

    LOAD_AB(0);
    STORE_AB(0);
    __syncthreads();

    for (int c = 0; c < 16; ++c) {
        const int cur = c & 1;
        if (c < 15) LOAD_AB(c + 1);

        const uint32_t* Ah = sAh[cur];
        const uint32_t* Al = sAl[cur];
        const uint32_t* Bh = sBh[cur];
        const uint32_t* Bl = sBl[cur];

        uint32_t ah[2][4], al[2][4];
#pragma unroll
        for (int mt = 0; mt < 2; ++mt) {
            const int mb = wm + mt * 16;
            const int r0 = (mb + g) * 12;
            const int r1 = (mb + g + 8) * 12;
            ah[mt][0] = Ah[r0 + tg];
            ah[mt][1] = Ah[r1 + tg];
            ah[mt][2] = Ah[r0 + tg + 4];
            ah[mt][3] = Ah[r1 + tg + 4];
            al[mt][0] = Al[r0 + tg];
            al[mt][1] = Al[r1 + tg];
            al[mt][2] = Al[r0 + tg + 4];
            al[mt][3] = Al[r1 + tg + 4];
        }
#pragma unroll
        for (int nt = 0; nt < 8; ++nt) {
            const int nb = (wn + nt * 8 + g) * 12;
            uint32_t bh[2] = { Bh[nb + tg], Bh[nb + tg + 4] };
            uint32_t bl[2] = { Bl[nb + tg], Bl[nb + tg + 4] };
#pragma unroll
            for (int mt = 0; mt < 2; ++mt) {
                mma16(acc[mt][nt], ah[mt], bh);
                mma16(acc[mt][nt], al[mt], bh);
                mma16(acc[mt][nt], ah[mt], bl);
            }
        }

        if (c < 15) STORE_AB(cur ^ 1);
        __syncthreads();
    }
#undef LOAD_AB
#undef STORE_AB

    // ================= fused z/r epilogue =================
    float* fsm = (float*)dsm;

    // stage Wlc/Wrc (stride 17), zero accum, load bf
#pragma unroll
    for (int i = 0; i < 8; ++i) {
        int idx = tid + i * 256;          // 0..2047
        int col = idx >> 4, c = idx & 15;
        fsm[col * 17 + c]        = g_Wlc[idx];
        fsm[2176 + col * 17 + c] = g_Wrc[idx];
    }
#pragma unroll
    for (int i = 0; i < 16; ++i) fsm[4352 + tid + i * 256] = 0.f;
    if (tid < 16) fsm[8448 + tid] = g_bf[tid];

    // bias + relu in place (h1 lives only in acc)
#pragma unroll
    for (int nt = 0; nt < 8; ++nt) {
        const int col = wn + nt * 8 + 2 * tg;
        const float2 bv = *(const float2*)(bias + col);
#pragma unroll
        for (int mt = 0; mt < 2; ++mt) {
            acc[mt][nt][0] = fmaxf(acc[mt][nt][0] + bv.x, 0.f);
            acc[mt][nt][1] = fmaxf(acc[mt][nt][1] + bv.y, 0.f);
            acc[mt][nt][2] = fmaxf(acc[mt][nt][2] + bv.x, 0.f);
            acc[mt][nt][3] = fmaxf(acc[mt][nt][3] + bv.y, 0.f);
        }
    }
    __syncthreads();

    const int rl0 = wm + g;   // thread's 4 rows: rl0, rl0+8, rl0+16, rl0+24
#pragma unroll
    for (int mat = 0; mat < 2; ++mat) {
        const float* wsm = fsm + mat * 2176;
        const int zbase = 4352 + mat * 16;
        for (int c = 0; c < 16; ++c) {
            float wv[16];
#pragma unroll
            for (int nt = 0; nt < 8; ++nt) {
                int col = wn + nt * 8 + 2 * tg;
                wv[nt * 2]     = wsm[col * 17 + c];
                wv[nt * 2 + 1] = wsm[(col + 1) * 17 + c];
            }
            float p00 = 0.f, p01 = 0.f, p10 = 0.f, p11 = 0.f;
#pragma unroll
            for (int nt = 0; nt < 8; ++nt) {
                p00 = fmaf(acc[0][nt][0], wv[nt * 2],     p00);
                p00 = fmaf(acc[0][nt][1], wv[nt * 2 + 1], p00);
                p01 = fmaf(acc[0][nt][2], wv[nt * 2],     p01);
                p01 = fmaf(acc[0][nt][3], wv[nt * 2 + 1], p01);
                p10 = fmaf(acc[1][nt][0], wv[nt * 2],     p10);
                p10 = fmaf(acc[1][nt][1], wv[nt * 2 + 1], p10);
                p11 = fmaf(acc[1][nt][2], wv[nt * 2],     p11);
                p11 = fmaf(acc[1][nt][3], wv[nt * 2 + 1], p11);
            }
            // reduce over the 4 tg lanes (lane bits 0-1)
#pragma unroll
            for (int m2 = 1; m2 <= 2; m2 <<= 1) {
                p00 += __shfl_xor_sync(0xffffffffu, p00, m2);
                p01 += __shfl_xor_sync(0xffffffffu, p01, m2);
                p10 += __shfl_xor_sync(0xffffffffu, p10, m2);
                p11 += __shfl_xor_sync(0xffffffffu, p11, m2);
            }
            if (tg == (c & 3)) {   // one lane per group commits (2-warp contention)
                atomicAdd(&fsm[zbase + (rl0     ) * 32 + c], p00);
                atomicAdd(&fsm[zbase + (rl0 +  8) * 32 + c], p01);
                atomicAdd(&fsm[zbase + (rl0 + 16) * 32 + c], p10);
                atomicAdd(&fsm[zbase + (rl0 + 24) * 32 + c], p11);
            }
        }
    }
    __syncthreads();

    // write z and r (+bf)
#pragma unroll
    for (int i = 0; i < 16; ++i) {
        int idx = tid + i * 256;          // 0..4095
        int rl = idx >> 5, cc = idx & 31;
        int n = m0 + rl;
        if (n < N_NODES) {
            float v = fsm[4352 + idx];
            if (cc < 16) g_z[n * 16 + cc] = v;
            else         g_r[n * 16 + (cc - 16)] = v + fsm[8448 + (cc - 16)];
        }
    }
}

// ---------------------------------------------------------------------------
// Kernel: out[n,c] = mean_{j->n}(z[j,c]) + r[n,c]   (gather, fused comb)
// ---------------------------------------------------------------------------
__global__ void __launch_bounds__(256) k_comb2(float* __restrict__ out) {
    int idx = blockIdx.x * 256 + threadIdx.x;
    int n = idx >> 4;
    if (n >= N_NODES) return;
    int c = idx & 15;
    int start = g_rowptr[n];
    int end   = g_rowptr[n + 1];
    float a0 = 0.f, a1 = 0.f;
    int j = start;
    for (; j + 1 < end; j += 2) {
        int s0 = g_csrc[j];
        int s1 = g_csrc[j + 1];
        a0 += g_z[s0 * 16 + c];
        a1 += g_z[s1 * 16 + c];
    }
    if (j < end) a0 += g_z[g_csrc[j] * 16 + c];
    int dg = end - start;
    float inv = 1.0f / (float)(dg > 1 ? dg : 1);
    out[idx] = fmaf(a0 + a1, inv, g_r[idx]);
}

// ---------------------------------------------------------------------------
extern "C" void kernel_launch(void* const* d_in, const int* in_sizes, int n_in,
                              void* d_out, int out_size) {
    const int*   entity = (const int*)d_in[0];
    const int*   eidx   = (const int*)d_in[1];
    const float* emb    = (const float*)d_in[2];
    const float* W1_l   = (const float*)d_in[3];
    const float* b1     = (const float*)d_in[4];
    const float* W1_r   = (const float*)d_in[5];
    const float* W2_l   = (const float*)d_in[6];
    const float* b2     = (const float*)d_in[7];
    const float* W2_r   = (const float*)d_in[8];
    const float* Wc     = (const float*)d_in[9];
    const float* bc     = (const float*)d_in[10];
    float* out = (float*)d_out;

    const int* src = eidx;            // edge_index[0]
    const int* dst = eidx + N_EDGES;  // edge_index[1]

    float* d_x = nullptr; cudaGetSymbolAddress((void**)&d_x, g_x);

    const int GEMM_BLOCKS = (N_NODES + 127) / 128;     // 391
    const int SCAN_BLOCKS = (N_NODES + 255) / 256;     // 196
    const int SMEM_LAYER  = 48 * 1024;

    cudaFuncSetAttribute(k_layer_fused, cudaFuncAttributeMaxDynamicSharedMemorySize,
                         SMEM_LAYER);

    // weight precompute (independent of node data)
    k_wprep<<<64, 256>>>(W1_l, W1_r);
    k_wfuse<<<2, 128>>>(W2_l, W2_r, Wc, b2, bc);
    // gather x + zero deg
    k_prep<<<(N_NODES + 7) / 8, 256>>>(entity, emb);
    // CSR build
    k_deg<<<(N_EDGES + 255) / 256, 256>>>(dst);
    k_scan1<<<SCAN_BLOCKS, 256>>>();
    k_scan2<<<1, 256>>>(SCAN_BLOCKS);
    k_scan3<<<SCAN_BLOCKS, 256>>>();
    k_fill<<<(N_EDGES + 255) / 256, 256>>>(src, dst);
    // gather-aggregate mean of x
    k_gather<<<(N_NODES + 7) / 8, 256>>>();
    // layer 1 + fused z/r epilogue (h1 never hits memory)
    k_layer_fused<<<GEMM_BLOCKS, 256, SMEM_LAYER>>>(b1, d_x);
    // fused gather mean of z + combine
    k_comb2<<<(N_NODES * 16 + 255) / 256, 256>>>(out);
}